// round 1
// baseline (speedup 1.0000x reference)
#include <cuda_runtime.h>
#include <cstdint>

// Problem constants (fixed by reference_code)
#define NB    8192      // batch rows
#define DIN   768       // input dim
#define DLAT  12288     // latent dim
#define KTOP  64        // top-k

// Scratch for top-k (idx, val) pairs, deterministic index order per row.
__device__ int   g_topk_idx[NB * KTOP];
__device__ float g_topk_val[NB * KTOP];

// ---------------------------------------------------------------------------
// Monotonic float<->uint key mapping: larger float => larger key (total order)
// ---------------------------------------------------------------------------
__device__ __forceinline__ unsigned f2key(float f) {
    unsigned u = __float_as_uint(f);
    return (u & 0x80000000u) ? ~u : (u | 0x80000000u);
}
__device__ __forceinline__ float key2f(unsigned k) {
    unsigned u = (k & 0x80000000u) ? (k ^ 0x80000000u) : ~k;
    return __uint_as_float(u);
}

// ---------------------------------------------------------------------------
// Encoder GEMM: C[NB, DLAT] = A[NB, DIN] @ W[DIN, DLAT] + bias[DLAT]
// Classic 128x128 block tile, 256 threads, 8x8 per thread, BK=16.
// ---------------------------------------------------------------------------
__global__ __launch_bounds__(256, 2)
void gemm_enc_kernel(const float* __restrict__ A,
                     const float* __restrict__ W,
                     const float* __restrict__ bias,
                     float* __restrict__ C) {
    __shared__ float As[16][128];   // transposed A tile: As[k][m]
    __shared__ float Bs[16][128];   // W tile: Bs[k][n]

    const int tid = threadIdx.x;
    const int tx  = tid & 15;       // 0..15 (n direction)
    const int ty  = tid >> 4;       // 0..15 (m direction)
    const int bm  = blockIdx.y * 128;
    const int bn  = blockIdx.x * 128;

    // A-load mapping: 128 rows x 16 cols = 512 float4; 2 per thread
    const int arow = tid >> 2;            // 0..63
    const int acol = (tid & 3) * 4;       // 0,4,8,12
    // B-load mapping: 16 rows x 128 cols = 512 float4; 2 per thread
    const int brow = tid >> 5;            // 0..7
    const int bcol = (tid & 31) * 4;      // 0..124

    float acc[8][8];
#pragma unroll
    for (int i = 0; i < 8; i++)
#pragma unroll
        for (int j = 0; j < 8; j++) acc[i][j] = 0.0f;

    for (int k0 = 0; k0 < DIN; k0 += 16) {
        float4 a0 = *(const float4*)&A[(size_t)(bm + arow)      * DIN + k0 + acol];
        float4 a1 = *(const float4*)&A[(size_t)(bm + arow + 64) * DIN + k0 + acol];
        As[acol + 0][arow]      = a0.x;
        As[acol + 1][arow]      = a0.y;
        As[acol + 2][arow]      = a0.z;
        As[acol + 3][arow]      = a0.w;
        As[acol + 0][arow + 64] = a1.x;
        As[acol + 1][arow + 64] = a1.y;
        As[acol + 2][arow + 64] = a1.z;
        As[acol + 3][arow + 64] = a1.w;

        float4 b0 = *(const float4*)&W[(size_t)(k0 + brow)     * DLAT + bn + bcol];
        float4 b1 = *(const float4*)&W[(size_t)(k0 + brow + 8) * DLAT + bn + bcol];
        *(float4*)&Bs[brow][bcol]     = b0;
        *(float4*)&Bs[brow + 8][bcol] = b1;

        __syncthreads();

#pragma unroll
        for (int k = 0; k < 16; k++) {
            float ar[8], br[8];
#pragma unroll
            for (int i = 0; i < 8; i++) ar[i] = As[k][ty * 8 + i];
#pragma unroll
            for (int j = 0; j < 8; j++) br[j] = Bs[k][tx * 8 + j];
#pragma unroll
            for (int i = 0; i < 8; i++)
#pragma unroll
                for (int j = 0; j < 8; j++)
                    acc[i][j] = fmaf(ar[i], br[j], acc[i][j]);
        }
        __syncthreads();
    }

    // Bias into regs
    float bb[8];
#pragma unroll
    for (int j = 0; j < 8; j++) bb[j] = bias[bn + tx * 8 + j];

    // Epilogue
#pragma unroll
    for (int i = 0; i < 8; i++) {
        const size_t rowoff = (size_t)(bm + ty * 8 + i) * DLAT + bn + tx * 8;
        float4 o0, o1;
        o0.x = acc[i][0] + bb[0]; o0.y = acc[i][1] + bb[1];
        o0.z = acc[i][2] + bb[2]; o0.w = acc[i][3] + bb[3];
        o1.x = acc[i][4] + bb[4]; o1.y = acc[i][5] + bb[5];
        o1.z = acc[i][6] + bb[6]; o1.w = acc[i][7] + bb[7];
        *(float4*)&C[rowoff]     = o0;
        *(float4*)&C[rowoff + 4] = o1;
    }
}

// ---------------------------------------------------------------------------
// Per-row exact top-k via 4-pass radix select on bit-keys (row staged in SMEM).
// In-place: z region already holds h; after this kernel, non-topk -> 0.
// Also emits (idx, val) pairs in deterministic index order for the decoder.
// ---------------------------------------------------------------------------
__global__ __launch_bounds__(256)
void topk_kernel(float* __restrict__ z) {
    extern __shared__ unsigned keys[];           // DLAT keys (48 KB)
    __shared__ int hist[256];
    __shared__ int cntA_s[256];
    __shared__ int cntT_s[256];
    __shared__ int tieList[KTOP];
    __shared__ int selB_s, kRem_s, totalA_s;

    const int tid = threadIdx.x;
    const int row = blockIdx.x;
    float* zr = z + (size_t)row * DLAT;

    for (int j = tid; j < DLAT; j += 256) keys[j] = f2key(zr[j]);
    __syncthreads();

    // --- radix select: find the KTOP-th largest key ---
    unsigned prefix = 0;
    int kRem = KTOP;
    for (int pass = 0; pass < 4; pass++) {
        const int shift = 24 - 8 * pass;
        hist[tid] = 0;
        __syncthreads();
        const unsigned mask = (pass == 0) ? 0u : (0xFFFFFFFFu << (shift + 8));
        for (int j = tid; j < DLAT; j += 256) {
            unsigned k = keys[j];
            if ((k & mask) == prefix)
                atomicAdd(&hist[(k >> shift) & 255], 1);
        }
        __syncthreads();
        if (tid == 0) {
            int cum = 0;
            for (int b = 255; b >= 0; b--) {
                cum += hist[b];
                if (cum >= kRem) {
                    selB_s = b;
                    kRem_s = kRem - (cum - hist[b]);
                    break;
                }
            }
        }
        __syncthreads();
        prefix |= ((unsigned)selB_s) << shift;
        kRem = kRem_s;
        __syncthreads();
    }
    const unsigned thr = prefix;   // exact KTOP-th largest key

    // --- per-thread contiguous segment counts (index-ordered compaction) ---
    const int seg = DLAT / 256;    // 48
    const int s0  = tid * seg;
    int ca = 0, ct = 0;
    for (int j = s0; j < s0 + seg; j++) {
        unsigned k = keys[j];
        ca += (k > thr);
        ct += (k == thr);
    }
    cntA_s[tid] = ca;
    cntT_s[tid] = ct;
    __syncthreads();
    if (tid == 0) {   // serial exclusive scan over 256 entries (cheap)
        int ra = 0, rt = 0;
        for (int i = 0; i < 256; i++) {
            int ta = cntA_s[i], tt = cntT_s[i];
            cntA_s[i] = ra; cntT_s[i] = rt;
            ra += ta; rt += tt;
        }
        totalA_s = ra;
    }
    __syncthreads();
    const int baseA  = cntA_s[tid];
    const int baseT  = cntT_s[tid];
    const int totalA = totalA_s;          // # strictly above threshold (< KTOP)
    const int nTie   = KTOP - totalA;     // ties accepted, lowest index first

    // --- emit (idx,val) pairs deterministically in index order ---
    int la = 0, lt = 0;
    for (int j = s0; j < s0 + seg; j++) {
        unsigned k = keys[j];
        if (k > thr) {
            int slot = baseA + la; la++;
            g_topk_idx[row * KTOP + slot] = j;
            g_topk_val[row * KTOP + slot] = key2f(k);
        } else if (k == thr) {
            int r = baseT + lt; lt++;
            if (r < nTie) {
                tieList[r] = j;
                int slot = totalA + r;
                g_topk_idx[row * KTOP + slot] = j;
                g_topk_val[row * KTOP + slot] = key2f(k);
            }
        }
    }
    __syncthreads();

    // --- coalesced in-place sparsification of z ---
    for (int j = tid; j < DLAT; j += 256) {
        unsigned k = keys[j];
        bool keep = (k > thr);
        if (k == thr) {
            for (int q = 0; q < nTie; q++)
                if (tieList[q] == j) { keep = true; break; }
        }
        zr[j] = keep ? key2f(k) : 0.0f;
    }
}

// ---------------------------------------------------------------------------
// Sparse decoder: recon[row, :] = sum_{i<KTOP} val_i * W_dec[idx_i, :] + b_dec
// One block per row; W_dec (37.7 MB) is L2-resident -> L2-bound gather.
// ---------------------------------------------------------------------------
__global__ __launch_bounds__(256)
void decoder_kernel(const float* __restrict__ Wd,
                    const float* __restrict__ bd,
                    float* __restrict__ recon) {
    __shared__ int   sidx[KTOP];
    __shared__ float sval[KTOP];
    const int tid = threadIdx.x;
    const int row = blockIdx.x;
    if (tid < KTOP) {
        sidx[tid] = g_topk_idx[row * KTOP + tid];
        sval[tid] = g_topk_val[row * KTOP + tid];
    }
    __syncthreads();

    float a0 = 0.0f, a1 = 0.0f, a2 = 0.0f;
#pragma unroll 4
    for (int i = 0; i < KTOP; i++) {
        const float* wr = Wd + (size_t)sidx[i] * DIN;
        const float  v  = sval[i];
        a0 = fmaf(v, wr[tid],       a0);
        a1 = fmaf(v, wr[tid + 256], a1);
        a2 = fmaf(v, wr[tid + 512], a2);
    }
    const size_t ro = (size_t)row * DIN;
    recon[ro + tid]       = a0 + bd[tid];
    recon[ro + tid + 256] = a1 + bd[tid + 256];
    recon[ro + tid + 512] = a2 + bd[tid + 512];
}

// ---------------------------------------------------------------------------
// kernel_launch: graph-capturable, allocation-free.
// Output layout: [recon (NB*DIN) | z (NB*DLAT)] fp32.
// ---------------------------------------------------------------------------
extern "C" void kernel_launch(void* const* d_in, const int* in_sizes, int n_in,
                              void* d_out, int out_size) {
    const float* x     = (const float*)d_in[0];
    const float* W_enc = (const float*)d_in[1];
    const float* b_enc = (const float*)d_in[2];
    const float* W_dec = (const float*)d_in[3];
    const float* b_dec = (const float*)d_in[4];
    // d_in[5] = k_top (fixed at 64 for this problem)

    float* recon = (float*)d_out;
    float* z     = (float*)d_out + (size_t)NB * DIN;

    // 1) encoder GEMM writes h directly into the z output region
    dim3 grid(DLAT / 128, NB / 128);
    gemm_enc_kernel<<<grid, 256>>>(x, W_enc, b_enc, z);

    // 2) exact per-row top-k, in-place sparsify z + emit (idx,val)
    const int smem = DLAT * (int)sizeof(unsigned);  // 48 KB dynamic
    cudaFuncSetAttribute(topk_kernel,
                         cudaFuncAttributeMaxDynamicSharedMemorySize, smem);
    topk_kernel<<<NB, 256, smem>>>(z);

    // 3) sparse decoder (gathers 64 W_dec rows per batch row)
    decoder_kernel<<<NB, 256>>>(W_dec, b_dec, recon);
}

// round 3
// speedup vs baseline: 1.3736x; 1.3736x over previous
#include <cuda_runtime.h>
#include <cuda_fp16.h>
#include <cstdint>

// Problem constants
#define NB    8192
#define DIN   768
#define DLAT  12288
#define KTOP  64
#define CAND_CAP 160
#define CAND_TARGET 96

// ---------------- device scratch (static; no runtime allocs) ----------------
__device__ __half g_Ah [(size_t)NB   * DIN];    // x in fp16            (12.6 MB)
__device__ __half g_Bth[(size_t)DLAT * DIN];    // W_enc^T fp16 K-major (18.9 MB)
__device__ float  g_WT [(size_t)DLAT * DIN];    // W_enc^T fp32         (37.7 MB)
__device__ __half g_Wd16[(size_t)DLAT * DIN];   // W_dec fp16           (18.9 MB)
__device__ __half g_H  [(size_t)NB   * DLAT];   // h approx fp16        (201 MB)
__device__ int    g_cand[(size_t)NB * CAND_CAP];
__device__ int    g_ncand[NB];
__device__ int    g_topk_idx[NB * KTOP];
__device__ float  g_topk_val[NB * KTOP];

// ---------------- helpers ----------------
__device__ __forceinline__ uint32_t smem_u32(const void* p) {
    uint32_t a;
    asm("{ .reg .u64 t; cvta.to.shared.u64 t, %1; cvt.u32.u64 %0, t; }" : "=r"(a) : "l"(p));
    return a;
}
#define CP_ASYNC16(dst, src) \
    asm volatile("cp.async.cg.shared.global [%0], [%1], 16;" :: "r"(dst), "l"(src))
#define CP_COMMIT() asm volatile("cp.async.commit_group;")
#define CP_WAIT(n)  asm volatile("cp.async.wait_group %0;" :: "n"(n))

#define LDMATRIX_X4(r0, r1, r2, r3, addr) \
    asm volatile("ldmatrix.sync.aligned.m8n8.x4.shared.b16 {%0,%1,%2,%3}, [%4];" \
                 : "=r"(r0), "=r"(r1), "=r"(r2), "=r"(r3) : "r"(addr))

#define MMA16816(c0, c1, c2, c3, a0, a1, a2, a3, b0, b1) \
    asm volatile("mma.sync.aligned.m16n8k16.row.col.f32.f16.f16.f32 " \
                 "{%0,%1,%2,%3},{%4,%5,%6,%7},{%8,%9},{%0,%1,%2,%3};" \
                 : "+f"(c0), "+f"(c1), "+f"(c2), "+f"(c3) \
                 : "r"(a0), "r"(a1), "r"(a2), "r"(a3), "r"(b0), "r"(b1))

// ---------------------------------------------------------------------------
// Prep kernels
// ---------------------------------------------------------------------------
__global__ void conv_x_kernel(const float* __restrict__ x) {
    int i = blockIdx.x * blockDim.x + threadIdx.x;
    if (i < NB * DIN) g_Ah[i] = __float2half_rn(x[i]);
}

__global__ void conv_wdec_kernel(const float* __restrict__ Wd) {
    int i = blockIdx.x * blockDim.x + threadIdx.x;
    if (i < DLAT * DIN) g_Wd16[i] = __float2half_rn(Wd[i]);
}

// W_enc [DIN][DLAT] -> W^T fp32 + fp16, [DLAT][DIN]
__global__ void conv_wenc_kernel(const float* __restrict__ W) {
    __shared__ float s[32][33];
    const int n0 = blockIdx.x * 32, k0 = blockIdx.y * 32;
    const int tx = threadIdx.x, ty0 = threadIdx.y;     // block 32x8
#pragma unroll
    for (int dy = 0; dy < 32; dy += 8)
        s[ty0 + dy][tx] = W[(size_t)(k0 + ty0 + dy) * DLAT + n0 + tx];
    __syncthreads();
#pragma unroll
    for (int dy = 0; dy < 32; dy += 8) {
        int ty = ty0 + dy;
        float v = s[tx][ty];                            // W[k0+tx][n0+ty]
        size_t o = (size_t)(n0 + ty) * DIN + k0 + tx;
        g_WT[o]  = v;
        g_Bth[o] = __float2half_rn(v);
    }
}

// ---------------------------------------------------------------------------
// fp16 tensor-core GEMM (mma.sync): H = Ah @ Bth^T (+bias), fp16 out
// BM=128, BN=128, BK=32 halfs, 3-stage cp.async pipeline, 256 threads.
// ---------------------------------------------------------------------------
#define GNIT (DIN / 32)     // 24

__global__ __launch_bounds__(256, 2)
void gemm_fp16_kernel(const float* __restrict__ bias) {
    extern __shared__ char sm[];
    const uint32_t sbase = smem_u32(sm);
    const int tid  = threadIdx.x;
    const int lane = tid & 31;
    const int wid  = tid >> 5;
    const int wm   = wid & 1;            // 2 warps in m
    const int wn   = wid >> 1;           // 4 warps in n
    const int bn   = blockIdx.x * 128;
    const int bm   = blockIdx.y * 128;

    // per-thread load mapping: 1024 16B-chunks/stage (A 512 | B 512), 4/thread
    float acc[4][4][4];
#pragma unroll
    for (int f = 0; f < 4; f++)
#pragma unroll
        for (int g = 0; g < 4; g++)
#pragma unroll
            for (int q = 0; q < 4; q++) acc[f][g][q] = 0.0f;

    auto load_stage = [&](int it) {
        const int s = it % 3;
        const int koff = it * 32;                    // halfs
        const uint32_t base = sbase + s * 16384;
#pragma unroll
        for (int q = 0; q < 4; q++) {
            int idx = tid + q * 256;                 // 0..1023
            int isB = idx >= 512;
            int id2 = idx - (isB ? 512 : 0);
            int r  = id2 >> 2;
            int ch = id2 & 3;
            const __half* src = isB
                ? (g_Bth + (size_t)(bn + r) * DIN + koff + ch * 8)
                : (g_Ah  + (size_t)(bm + r) * DIN + koff + ch * 8);
            uint32_t dst = base + (isB ? 8192 : 0) + r * 64 +
                           ((ch ^ ((r >> 1) & 3)) << 4);
            CP_ASYNC16(dst, src);
        }
        CP_COMMIT();
    };

    load_stage(0);
    load_stage(1);

    for (int it = 0; it < GNIT; it++) {
        if (it + 2 < GNIT) CP_WAIT(1); else CP_WAIT(0);
        __syncthreads();
        if (it + 2 < GNIT) load_stage(it + 2);

        const uint32_t sA = sbase + (it % 3) * 16384;
        const uint32_t sB = sA + 8192;
#pragma unroll
        for (int ks = 0; ks < 2; ks++) {
            uint32_t a[4][4], b[4][2];
#pragma unroll
            for (int f = 0; f < 4; f++) {
                int q  = lane >> 3;
                int r  = wm * 64 + f * 16 + (lane & 7) + ((q & 1) << 3);
                int ch = ks * 2 + (q >> 1);
                uint32_t addr = sA + r * 64 + ((ch ^ ((r >> 1) & 3)) << 4);
                LDMATRIX_X4(a[f][0], a[f][1], a[f][2], a[f][3], addr);
            }
#pragma unroll
            for (int p = 0; p < 2; p++) {
                int q  = lane >> 3;
                int n  = wn * 32 + p * 16 + ((q >> 1) << 3) + (lane & 7);
                int ch = ks * 2 + (q & 1);
                uint32_t addr = sB + n * 64 + ((ch ^ ((n >> 1) & 3)) << 4);
                LDMATRIX_X4(b[2 * p][0], b[2 * p][1], b[2 * p + 1][0], b[2 * p + 1][1], addr);
            }
#pragma unroll
            for (int f = 0; f < 4; f++)
#pragma unroll
                for (int g = 0; g < 4; g++)
                    MMA16816(acc[f][g][0], acc[f][g][1], acc[f][g][2], acc[f][g][3],
                             a[f][0], a[f][1], a[f][2], a[f][3],
                             b[g][0], b[g][1]);
        }
        __syncthreads();
    }

    // epilogue: +bias, convert fp16, store
#pragma unroll
    for (int f = 0; f < 4; f++) {
#pragma unroll
        for (int g = 0; g < 4; g++) {
            int r0 = bm + wm * 64 + f * 16 + (lane >> 2);
            int c0 = bn + wn * 32 + g * 8 + (lane & 3) * 2;
            float b0 = bias[c0], b1 = bias[c0 + 1];
            __half2 h0 = __floats2half2_rn(acc[f][g][0] + b0, acc[f][g][1] + b1);
            __half2 h1 = __floats2half2_rn(acc[f][g][2] + b0, acc[f][g][3] + b1);
            *(__half2*)(g_H + (size_t)r0 * DLAT + c0)       = h0;
            *(__half2*)(g_H + (size_t)(r0 + 8) * DLAT + c0) = h1;
        }
    }
}

// ---------------------------------------------------------------------------
// Top-96 candidate selection per row (2-pass radix on 16-bit keys)
// ---------------------------------------------------------------------------
__device__ __forceinline__ unsigned f2key16(unsigned u) {
    return (u & 0x8000u) ? ((~u) & 0xFFFFu) : (u | 0x8000u);
}

__global__ __launch_bounds__(256)
void topk16_kernel() {
    __shared__ uint16_t keys[DLAT];
    __shared__ int hist[256];
    __shared__ int cnt_s[256];
    __shared__ int selB_s, kRem_s;

    const int tid = threadIdx.x;
    const int row = blockIdx.x;
    const uint4* hrow = (const uint4*)(g_H + (size_t)row * DLAT);

    for (int i = tid; i < DLAT / 8; i += 256) {
        uint4 v = hrow[i];
        unsigned w[4] = {v.x, v.y, v.z, v.w};
#pragma unroll
        for (int q = 0; q < 4; q++) {
            keys[i * 8 + q * 2 + 0] = (uint16_t)f2key16(w[q] & 0xFFFFu);
            keys[i * 8 + q * 2 + 1] = (uint16_t)f2key16(w[q] >> 16);
        }
    }
    __syncthreads();

    // pass 1: high byte
    hist[tid] = 0;
    __syncthreads();
    for (int j = tid; j < DLAT; j += 256) atomicAdd(&hist[keys[j] >> 8], 1);
    __syncthreads();
    if (tid == 0) {
        int cum = 0;
        for (int b = 255; b >= 0; b--) {
            cum += hist[b];
            if (cum >= CAND_TARGET) { selB_s = b; kRem_s = CAND_TARGET - (cum - hist[b]); break; }
        }
    }
    __syncthreads();
    const int b1 = selB_s;
    const int kRem = kRem_s;
    __syncthreads();

    // pass 2: low byte within bucket b1
    hist[tid] = 0;
    __syncthreads();
    for (int j = tid; j < DLAT; j += 256) {
        unsigned k = keys[j];
        if ((int)(k >> 8) == b1) atomicAdd(&hist[k & 255], 1);
    }
    __syncthreads();
    if (tid == 0) {
        int cum = 0;
        for (int b = 255; b >= 0; b--) {
            cum += hist[b];
            if (cum >= kRem) { selB_s = b; break; }
        }
    }
    __syncthreads();
    const unsigned thr = ((unsigned)b1 << 8) | (unsigned)selB_s;

    // emit all keys >= thr in ascending-index order (capped)
    const int seg = DLAT / 256;   // 48
    const int s0  = tid * seg;
    int c = 0;
    for (int j = s0; j < s0 + seg; j++) c += (keys[j] >= thr);
    cnt_s[tid] = c;
    __syncthreads();
    if (tid == 0) {
        int run = 0;
        for (int i = 0; i < 256; i++) { int t = cnt_s[i]; cnt_s[i] = run; run += t; }
        g_ncand[row] = (run < CAND_CAP) ? run : CAND_CAP;
    }
    __syncthreads();
    int base = cnt_s[tid], l = 0;
    for (int j = s0; j < s0 + seg; j++) {
        if (keys[j] >= thr) {
            int slot = base + l; l++;
            if (slot < CAND_CAP) g_cand[(size_t)row * CAND_CAP + slot] = j;
        }
    }
}

// ---------------------------------------------------------------------------
// Exact fp32 rescore of candidates + exact top-64 + z write (zeros + scatter)
// Accumulation is sequential over k (matches R1 GEMM / reference ordering).
// ---------------------------------------------------------------------------
__global__ __launch_bounds__(128)
void rescore_kernel(const float* __restrict__ x,
                    const float* __restrict__ b_enc,
                    float* __restrict__ z) {
    __shared__ float xs[DIN];
    __shared__ int   cidx[CAND_CAP];
    __shared__ float cval[CAND_CAP];
    __shared__ int   slotArr[CAND_CAP];
    __shared__ unsigned char sel[CAND_CAP];

    const int tid = threadIdx.x;
    const int row = blockIdx.x;
    const int nc  = g_ncand[row];

    for (int i = tid; i < DIN; i += 128) xs[i] = x[(size_t)row * DIN + i];
    for (int i = tid; i < nc; i += 128)  cidx[i] = g_cand[(size_t)row * CAND_CAP + i];
    __syncthreads();

    for (int t = tid; t < nc; t += 128) {
        const int j = cidx[t];
        const float* w = g_WT + (size_t)j * DIN;
        float acc = 0.0f;
#pragma unroll 4
        for (int k = 0; k < DIN; k++) acc = fmaf(xs[k], w[k], acc);
        cval[t] = acc + b_enc[j];
    }
    __syncthreads();

    for (int t = tid; t < nc; t += 128) {
        const float v = cval[t];
        const int   j = cidx[t];
        int r = 0;
        for (int q = 0; q < nc; q++) {
            float vq = cval[q];
            r += (vq > v) || (vq == v && cidx[q] < j);
        }
        sel[t] = (r < KTOP) ? 1 : 0;
    }
    __syncthreads();
    if (tid == 0) {
        int s = 0;
        for (int q = 0; q < nc; q++) { slotArr[q] = s; s += sel[q]; }
    }
    __syncthreads();

    // z row: zeros then scatter selected
    float4* zr4 = (float4*)(z + (size_t)row * DLAT);
    const float4 zf = {0.f, 0.f, 0.f, 0.f};
    for (int i = tid; i < DLAT / 4; i += 128) zr4[i] = zf;
    __syncthreads();
    for (int t = tid; t < nc; t += 128) {
        if (sel[t]) {
            int s = slotArr[t];
            g_topk_idx[row * KTOP + s] = cidx[t];
            g_topk_val[row * KTOP + s] = cval[t];
            z[(size_t)row * DLAT + cidx[t]] = cval[t];
        }
    }
}

// ---------------------------------------------------------------------------
// Sparse decoder with fp16 W_dec (values fp32), index-ascending summation
// ---------------------------------------------------------------------------
__global__ __launch_bounds__(128)
void decoder_kernel(const float* __restrict__ bd, float* __restrict__ recon) {
    __shared__ int   sidx[KTOP];
    __shared__ float sval[KTOP];
    const int tid = threadIdx.x;
    const int row = blockIdx.x;
    if (tid < KTOP) {
        sidx[tid] = g_topk_idx[row * KTOP + tid];
        sval[tid] = g_topk_val[row * KTOP + tid];
    }
    __syncthreads();

    float a0 = 0, a1 = 0, a2 = 0, a3 = 0, a4 = 0, a5 = 0;
#pragma unroll 4
    for (int i = 0; i < KTOP; i++) {
        const __half2* w = (const __half2*)(g_Wd16 + (size_t)sidx[i] * DIN);
        const float v = sval[i];
        float2 p0 = __half22float2(w[tid]);
        float2 p1 = __half22float2(w[tid + 128]);
        float2 p2 = __half22float2(w[tid + 256]);
        a0 = fmaf(v, p0.x, a0); a1 = fmaf(v, p0.y, a1);
        a2 = fmaf(v, p1.x, a2); a3 = fmaf(v, p1.y, a3);
        a4 = fmaf(v, p2.x, a4); a5 = fmaf(v, p2.y, a5);
    }
    float* rr = recon + (size_t)row * DIN;
    rr[2 * tid]        = a0 + bd[2 * tid];
    rr[2 * tid + 1]    = a1 + bd[2 * tid + 1];
    rr[2 * tid + 256]  = a2 + bd[2 * tid + 256];
    rr[2 * tid + 257]  = a3 + bd[2 * tid + 257];
    rr[2 * tid + 512]  = a4 + bd[2 * tid + 512];
    rr[2 * tid + 513]  = a5 + bd[2 * tid + 513];
}

// ---------------------------------------------------------------------------
extern "C" void kernel_launch(void* const* d_in, const int* in_sizes, int n_in,
                              void* d_out, int out_size) {
    const float* x     = (const float*)d_in[0];
    const float* W_enc = (const float*)d_in[1];
    const float* b_enc = (const float*)d_in[2];
    const float* W_dec = (const float*)d_in[3];
    const float* b_dec = (const float*)d_in[4];

    float* recon = (float*)d_out;
    float* z     = (float*)d_out + (size_t)NB * DIN;

    // prep: fp16 copies + W_enc transpose
    conv_x_kernel<<<(NB * DIN + 255) / 256, 256>>>(x);
    conv_wdec_kernel<<<(DLAT * DIN + 255) / 256, 256>>>(W_dec);
    conv_wenc_kernel<<<dim3(DLAT / 32, DIN / 32), dim3(32, 8)>>>(W_enc);

    // approximate encoder GEMM (fp16 tensor cores) -> g_H
    const int gemm_smem = 3 * 16384;
    cudaFuncSetAttribute(gemm_fp16_kernel,
                         cudaFuncAttributeMaxDynamicSharedMemorySize, gemm_smem);
    gemm_fp16_kernel<<<dim3(DLAT / 128, NB / 128), 256, gemm_smem>>>(b_enc);

    // top-96 candidates per row
    topk16_kernel<<<NB, 256>>>();

    // exact fp32 rescore + top-64 + z
    rescore_kernel<<<NB, 128>>>(x, b_enc, z);

    // sparse decoder
    decoder_kernel<<<NB, 128>>>(b_dec, recon);
}

// round 4
// speedup vs baseline: 3.6505x; 2.6576x over previous
#include <cuda_runtime.h>
#include <cuda_fp16.h>
#include <cstdint>

// Problem constants
#define NB    8192
#define DIN   768
#define DLAT  12288
#define KTOP  64
#define CAND_CAP 160
#define CAND_TARGET 96

// ---------------- device scratch (static; no runtime allocs) ----------------
__device__ __half g_Ah [(size_t)NB   * DIN];    // x in fp16            (12.6 MB)
__device__ __half g_Bth[(size_t)DLAT * DIN];    // W_enc^T fp16 K-major (18.9 MB)
__device__ float  g_WT [(size_t)DLAT * DIN];    // W_enc^T fp32         (37.7 MB)
__device__ __half g_H  [(size_t)NB   * DLAT];   // h approx fp16        (201 MB)
__device__ int    g_cand[(size_t)NB * CAND_CAP];
__device__ int    g_ncand[NB];
__device__ int    g_topk_idx[NB * KTOP];
__device__ float  g_topk_val[NB * KTOP];

// ---------------- helpers ----------------
__device__ __forceinline__ uint32_t smem_u32(const void* p) {
    uint32_t a;
    asm("{ .reg .u64 t; cvta.to.shared.u64 t, %1; cvt.u32.u64 %0, t; }" : "=r"(a) : "l"(p));
    return a;
}
#define CP_ASYNC16(dst, src) \
    asm volatile("cp.async.cg.shared.global [%0], [%1], 16;" :: "r"(dst), "l"(src))
#define CP_COMMIT() asm volatile("cp.async.commit_group;")
#define CP_WAIT(n)  asm volatile("cp.async.wait_group %0;" :: "n"(n))

#define LDMATRIX_X4(r0, r1, r2, r3, addr) \
    asm volatile("ldmatrix.sync.aligned.m8n8.x4.shared.b16 {%0,%1,%2,%3}, [%4];" \
                 : "=r"(r0), "=r"(r1), "=r"(r2), "=r"(r3) : "r"(addr))

#define MMA16816(c0, c1, c2, c3, a0, a1, a2, a3, b0, b1) \
    asm volatile("mma.sync.aligned.m16n8k16.row.col.f32.f16.f16.f32 " \
                 "{%0,%1,%2,%3},{%4,%5,%6,%7},{%8,%9},{%0,%1,%2,%3};" \
                 : "+f"(c0), "+f"(c1), "+f"(c2), "+f"(c3) \
                 : "r"(a0), "r"(a1), "r"(a2), "r"(a3), "r"(b0), "r"(b1))

// ---------------------------------------------------------------------------
// Prep kernels
// ---------------------------------------------------------------------------
__global__ void conv_x_kernel(const float* __restrict__ x) {
    int i = blockIdx.x * blockDim.x + threadIdx.x;
    if (i < NB * DIN) g_Ah[i] = __float2half_rn(x[i]);
}

// W_enc [DIN][DLAT] -> W^T fp32 + fp16, [DLAT][DIN]
__global__ void conv_wenc_kernel(const float* __restrict__ W) {
    __shared__ float s[32][33];
    const int n0 = blockIdx.x * 32, k0 = blockIdx.y * 32;
    const int tx = threadIdx.x, ty0 = threadIdx.y;     // block 32x8
#pragma unroll
    for (int dy = 0; dy < 32; dy += 8)
        s[ty0 + dy][tx] = W[(size_t)(k0 + ty0 + dy) * DLAT + n0 + tx];
    __syncthreads();
#pragma unroll
    for (int dy = 0; dy < 32; dy += 8) {
        int ty = ty0 + dy;
        float v = s[tx][ty];                            // W[k0+tx][n0+ty]
        size_t o = (size_t)(n0 + ty) * DIN + k0 + tx;
        g_WT[o]  = v;
        g_Bth[o] = __float2half_rn(v);
    }
}

// ---------------------------------------------------------------------------
// fp16 tensor-core GEMM (mma.sync): H = Ah @ Bth^T (+bias), fp16 out
// BM=128, BN=128, BK=32 halfs, 3-stage cp.async pipeline, 256 threads.
// ---------------------------------------------------------------------------
#define GNIT (DIN / 32)     // 24

__global__ __launch_bounds__(256, 2)
void gemm_fp16_kernel(const float* __restrict__ bias) {
    extern __shared__ char sm[];
    const uint32_t sbase = smem_u32(sm);
    const int tid  = threadIdx.x;
    const int lane = tid & 31;
    const int wid  = tid >> 5;
    const int wm   = wid & 1;            // 2 warps in m
    const int wn   = wid >> 1;           // 4 warps in n
    const int bn   = blockIdx.x * 128;
    const int bm   = blockIdx.y * 128;

    float acc[4][4][4];
#pragma unroll
    for (int f = 0; f < 4; f++)
#pragma unroll
        for (int g = 0; g < 4; g++)
#pragma unroll
            for (int q = 0; q < 4; q++) acc[f][g][q] = 0.0f;

    auto load_stage = [&](int it) {
        const int s = it % 3;
        const int koff = it * 32;                    // halfs
        const uint32_t base = sbase + s * 16384;
#pragma unroll
        for (int q = 0; q < 4; q++) {
            int idx = tid + q * 256;                 // 0..1023
            int isB = idx >= 512;
            int id2 = idx - (isB ? 512 : 0);
            int r  = id2 >> 2;
            int ch = id2 & 3;
            const __half* src = isB
                ? (g_Bth + (size_t)(bn + r) * DIN + koff + ch * 8)
                : (g_Ah  + (size_t)(bm + r) * DIN + koff + ch * 8);
            uint32_t dst = base + (isB ? 8192 : 0) + r * 64 +
                           ((ch ^ ((r >> 1) & 3)) << 4);
            CP_ASYNC16(dst, src);
        }
        CP_COMMIT();
    };

    load_stage(0);
    load_stage(1);

    for (int it = 0; it < GNIT; it++) {
        if (it + 2 < GNIT) CP_WAIT(1); else CP_WAIT(0);
        __syncthreads();
        if (it + 2 < GNIT) load_stage(it + 2);

        const uint32_t sA = sbase + (it % 3) * 16384;
        const uint32_t sB = sA + 8192;
#pragma unroll
        for (int ks = 0; ks < 2; ks++) {
            uint32_t a[4][4], b[4][2];
#pragma unroll
            for (int f = 0; f < 4; f++) {
                int q  = lane >> 3;
                int r  = wm * 64 + f * 16 + (lane & 7) + ((q & 1) << 3);
                int ch = ks * 2 + (q >> 1);
                uint32_t addr = sA + r * 64 + ((ch ^ ((r >> 1) & 3)) << 4);
                LDMATRIX_X4(a[f][0], a[f][1], a[f][2], a[f][3], addr);
            }
#pragma unroll
            for (int p = 0; p < 2; p++) {
                int q  = lane >> 3;
                int n  = wn * 32 + p * 16 + ((q >> 1) << 3) + (lane & 7);
                int ch = ks * 2 + (q & 1);
                uint32_t addr = sB + n * 64 + ((ch ^ ((n >> 1) & 3)) << 4);
                LDMATRIX_X4(b[2 * p][0], b[2 * p][1], b[2 * p + 1][0], b[2 * p + 1][1], addr);
            }
#pragma unroll
            for (int f = 0; f < 4; f++)
#pragma unroll
                for (int g = 0; g < 4; g++)
                    MMA16816(acc[f][g][0], acc[f][g][1], acc[f][g][2], acc[f][g][3],
                             a[f][0], a[f][1], a[f][2], a[f][3],
                             b[g][0], b[g][1]);
        }
        __syncthreads();
    }

    // epilogue: +bias, convert fp16, store
#pragma unroll
    for (int f = 0; f < 4; f++) {
#pragma unroll
        for (int g = 0; g < 4; g++) {
            int r0 = bm + wm * 64 + f * 16 + (lane >> 2);
            int c0 = bn + wn * 32 + g * 8 + (lane & 3) * 2;
            float b0 = bias[c0], b1 = bias[c0 + 1];
            __half2 h0 = __floats2half2_rn(acc[f][g][0] + b0, acc[f][g][1] + b1);
            __half2 h1 = __floats2half2_rn(acc[f][g][2] + b0, acc[f][g][3] + b1);
            *(__half2*)(g_H + (size_t)r0 * DLAT + c0)       = h0;
            *(__half2*)(g_H + (size_t)(r0 + 8) * DLAT + c0) = h1;
        }
    }
}

// ---------------------------------------------------------------------------
// Top-96 candidate selection per row (2-pass radix on 16-bit keys)
// ---------------------------------------------------------------------------
__device__ __forceinline__ unsigned f2key16(unsigned u) {
    return (u & 0x8000u) ? ((~u) & 0xFFFFu) : (u | 0x8000u);
}

__global__ __launch_bounds__(256)
void topk16_kernel() {
    __shared__ uint16_t keys[DLAT];
    __shared__ int hist[256];
    __shared__ int cnt_s[256];
    __shared__ int selB_s, kRem_s;

    const int tid = threadIdx.x;
    const int row = blockIdx.x;
    const uint4* hrow = (const uint4*)(g_H + (size_t)row * DLAT);

    for (int i = tid; i < DLAT / 8; i += 256) {
        uint4 v = hrow[i];
        unsigned w[4] = {v.x, v.y, v.z, v.w};
#pragma unroll
        for (int q = 0; q < 4; q++) {
            keys[i * 8 + q * 2 + 0] = (uint16_t)f2key16(w[q] & 0xFFFFu);
            keys[i * 8 + q * 2 + 1] = (uint16_t)f2key16(w[q] >> 16);
        }
    }
    __syncthreads();

    // pass 1: high byte
    hist[tid] = 0;
    __syncthreads();
    for (int j = tid; j < DLAT; j += 256) atomicAdd(&hist[keys[j] >> 8], 1);
    __syncthreads();
    if (tid == 0) {
        int cum = 0;
        for (int b = 255; b >= 0; b--) {
            cum += hist[b];
            if (cum >= CAND_TARGET) { selB_s = b; kRem_s = CAND_TARGET - (cum - hist[b]); break; }
        }
    }
    __syncthreads();
    const int b1 = selB_s;
    const int kRem = kRem_s;
    __syncthreads();

    // pass 2: low byte within bucket b1
    hist[tid] = 0;
    __syncthreads();
    for (int j = tid; j < DLAT; j += 256) {
        unsigned k = keys[j];
        if ((int)(k >> 8) == b1) atomicAdd(&hist[k & 255], 1);
    }
    __syncthreads();
    if (tid == 0) {
        int cum = 0;
        for (int b = 255; b >= 0; b--) {
            cum += hist[b];
            if (cum >= kRem) { selB_s = b; break; }
        }
    }
    __syncthreads();
    const unsigned thr = ((unsigned)b1 << 8) | (unsigned)selB_s;

    // emit all keys >= thr in ascending-index order (capped)
    const int seg = DLAT / 256;   // 48
    const int s0  = tid * seg;
    int c = 0;
    for (int j = s0; j < s0 + seg; j++) c += (keys[j] >= thr);
    cnt_s[tid] = c;
    __syncthreads();
    if (tid == 0) {
        int run = 0;
        for (int i = 0; i < 256; i++) { int t = cnt_s[i]; cnt_s[i] = run; run += t; }
        g_ncand[row] = (run < CAND_CAP) ? run : CAND_CAP;
    }
    __syncthreads();
    int base = cnt_s[tid], l = 0;
    for (int j = s0; j < s0 + seg; j++) {
        if (keys[j] >= thr) {
            int slot = base + l; l++;
            if (slot < CAND_CAP) g_cand[(size_t)row * CAND_CAP + slot] = j;
        }
    }
}

// ---------------------------------------------------------------------------
// Exact fp32 rescore: ONE WARP PER CANDIDATE (coalesced float4 gather of the
// W^T row, shfl reduction), then exact top-64 among candidates and z write.
// ---------------------------------------------------------------------------
__global__ __launch_bounds__(128)
void rescore_kernel(const float* __restrict__ x,
                    const float* __restrict__ b_enc,
                    float* __restrict__ z) {
    __shared__ float xs[DIN];
    __shared__ int   cidx[CAND_CAP];
    __shared__ float cval[CAND_CAP];
    __shared__ int   slotArr[CAND_CAP];
    __shared__ unsigned char sel[CAND_CAP];

    const int tid  = threadIdx.x;
    const int lane = tid & 31;
    const int wid  = tid >> 5;         // 4 warps
    const int row  = blockIdx.x;
    const int nc   = g_ncand[row];

    for (int i = tid; i < DIN / 4; i += 128)
        *(float4*)&xs[i * 4] = *(const float4*)&x[(size_t)row * DIN + i * 4];
    for (int i = tid; i < nc; i += 128)
        cidx[i] = g_cand[(size_t)row * CAND_CAP + i];
    __syncthreads();

    // warp-per-candidate coalesced dot products (768 = 192 float4 = 6/lane)
    const float4* x4 = (const float4*)xs;
    for (int t = wid; t < nc; t += 4) {
        const int j = cidx[t];
        const float4* w4 = (const float4*)(g_WT + (size_t)j * DIN);
        float acc = 0.0f;
#pragma unroll
        for (int q = 0; q < 6; q++) {
            const int p = lane + q * 32;
            float4 wv = w4[p];
            float4 xv = x4[p];
            acc = fmaf(wv.x, xv.x, acc);
            acc = fmaf(wv.y, xv.y, acc);
            acc = fmaf(wv.z, xv.z, acc);
            acc = fmaf(wv.w, xv.w, acc);
        }
#pragma unroll
        for (int o = 16; o; o >>= 1)
            acc += __shfl_xor_sync(0xFFFFFFFFu, acc, o);
        if (lane == 0) cval[t] = acc + b_enc[j];
    }
    __syncthreads();

    // exact rank by (value desc, index asc)
    for (int t = tid; t < nc; t += 128) {
        const float v = cval[t];
        const int   j = cidx[t];
        int r = 0;
        for (int q = 0; q < nc; q++) {
            float vq = cval[q];
            r += (vq > v) || (vq == v && cidx[q] < j);
        }
        sel[t] = (r < KTOP) ? 1 : 0;
    }
    __syncthreads();
    if (tid == 0) {
        int s = 0;
        for (int q = 0; q < nc; q++) { slotArr[q] = s; s += sel[q]; }
    }
    __syncthreads();

    // z row: zeros then scatter selected
    float4* zr4 = (float4*)(z + (size_t)row * DLAT);
    const float4 zf = {0.f, 0.f, 0.f, 0.f};
    for (int i = tid; i < DLAT / 4; i += 128) zr4[i] = zf;
    __syncthreads();
    for (int t = tid; t < nc; t += 128) {
        if (sel[t]) {
            int s = slotArr[t];
            g_topk_idx[row * KTOP + s] = cidx[t];
            g_topk_val[row * KTOP + s] = cval[t];
            z[(size_t)row * DLAT + cidx[t]] = cval[t];
        }
    }
}

// ---------------------------------------------------------------------------
// Sparse decoder, fp32 W_dec (rows contiguous; all lanes read same row =>
// coalesced). recon[row,:] = sum val_i * W_dec[idx_i,:] + b_dec
// ---------------------------------------------------------------------------
__global__ __launch_bounds__(256)
void decoder_kernel(const float* __restrict__ Wd,
                    const float* __restrict__ bd,
                    float* __restrict__ recon) {
    __shared__ int   sidx[KTOP];
    __shared__ float sval[KTOP];
    const int tid = threadIdx.x;
    const int row = blockIdx.x;
    if (tid < KTOP) {
        sidx[tid] = g_topk_idx[row * KTOP + tid];
        sval[tid] = g_topk_val[row * KTOP + tid];
    }
    __syncthreads();

    float a0 = 0.0f, a1 = 0.0f, a2 = 0.0f;
#pragma unroll 4
    for (int i = 0; i < KTOP; i++) {
        const float* wr = Wd + (size_t)sidx[i] * DIN;
        const float  v  = sval[i];
        a0 = fmaf(v, wr[tid],       a0);
        a1 = fmaf(v, wr[tid + 256], a1);
        a2 = fmaf(v, wr[tid + 512], a2);
    }
    const size_t ro = (size_t)row * DIN;
    recon[ro + tid]       = a0 + bd[tid];
    recon[ro + tid + 256] = a1 + bd[tid + 256];
    recon[ro + tid + 512] = a2 + bd[tid + 512];
}

// ---------------------------------------------------------------------------
extern "C" void kernel_launch(void* const* d_in, const int* in_sizes, int n_in,
                              void* d_out, int out_size) {
    const float* x     = (const float*)d_in[0];
    const float* W_enc = (const float*)d_in[1];
    const float* b_enc = (const float*)d_in[2];
    const float* W_dec = (const float*)d_in[3];
    const float* b_dec = (const float*)d_in[4];

    float* recon = (float*)d_out;
    float* z     = (float*)d_out + (size_t)NB * DIN;

    // prep: fp16 x + W_enc transpose (fp32 + fp16)
    conv_x_kernel<<<(NB * DIN + 255) / 256, 256>>>(x);
    conv_wenc_kernel<<<dim3(DLAT / 32, DIN / 32), dim3(32, 8)>>>(W_enc);

    // approximate encoder GEMM (fp16 tensor cores) -> g_H
    const int gemm_smem = 3 * 16384;
    cudaFuncSetAttribute(gemm_fp16_kernel,
                         cudaFuncAttributeMaxDynamicSharedMemorySize, gemm_smem);
    gemm_fp16_kernel<<<dim3(DLAT / 128, NB / 128), 256, gemm_smem>>>(b_enc);

    // top-96 candidates per row
    topk16_kernel<<<NB, 256>>>();

    // exact fp32 rescore + top-64 + z (coalesced warp-per-candidate gather)
    rescore_kernel<<<NB, 128>>>(x, b_enc, z);

    // sparse decoder (fp32 weights straight from input)
    decoder_kernel<<<NB, 256>>>(W_dec, b_dec, recon);
}

// round 5
// speedup vs baseline: 4.2353x; 1.1602x over previous
#include <cuda_runtime.h>
#include <cuda_fp16.h>
#include <cstdint>

// Problem constants
#define NB    8192
#define DIN   768
#define DLAT  12288
#define KTOP  64
#define CAND_CAP 160
#define CAND_TARGET 96

// ---------------- device scratch (static; no runtime allocs) ----------------
__device__ __half g_Ah [(size_t)NB   * DIN];    // x in fp16
__device__ __half g_Bth[(size_t)DLAT * DIN];    // W_enc^T fp16 K-major
__device__ float  g_WT [(size_t)DLAT * DIN];    // W_enc^T fp32
__device__ __half g_H  [(size_t)NB   * DLAT];   // h approx fp16
__device__ int    g_cand[(size_t)NB * CAND_CAP];
__device__ int    g_ncand[NB];
__device__ int    g_topk_idx[NB * KTOP];
__device__ float  g_topk_val[NB * KTOP];

// ---------------- helpers ----------------
__device__ __forceinline__ uint32_t smem_u32(const void* p) {
    uint32_t a;
    asm("{ .reg .u64 t; cvta.to.shared.u64 t, %1; cvt.u32.u64 %0, t; }" : "=r"(a) : "l"(p));
    return a;
}
#define CP_ASYNC16(dst, src) \
    asm volatile("cp.async.cg.shared.global [%0], [%1], 16;" :: "r"(dst), "l"(src))
#define CP_COMMIT() asm volatile("cp.async.commit_group;")
#define CP_WAIT(n)  asm volatile("cp.async.wait_group %0;" :: "n"(n))

#define LDMATRIX_X4(r0, r1, r2, r3, addr) \
    asm volatile("ldmatrix.sync.aligned.m8n8.x4.shared.b16 {%0,%1,%2,%3}, [%4];" \
                 : "=r"(r0), "=r"(r1), "=r"(r2), "=r"(r3) : "r"(addr))

#define MMA16816(c0, c1, c2, c3, a0, a1, a2, a3, b0, b1) \
    asm volatile("mma.sync.aligned.m16n8k16.row.col.f32.f16.f16.f32 " \
                 "{%0,%1,%2,%3},{%4,%5,%6,%7},{%8,%9},{%0,%1,%2,%3};" \
                 : "+f"(c0), "+f"(c1), "+f"(c2), "+f"(c3) \
                 : "r"(a0), "r"(a1), "r"(a2), "r"(a3), "r"(b0), "r"(b1))

// ---------------------------------------------------------------------------
// Prep kernels
// ---------------------------------------------------------------------------
__global__ void conv_x_kernel(const float* __restrict__ x) {
    int i = blockIdx.x * blockDim.x + threadIdx.x;
    if (i < NB * DIN) g_Ah[i] = __float2half_rn(x[i]);
}

// W_enc [DIN][DLAT] -> W^T fp32 + fp16, [DLAT][DIN]
__global__ void conv_wenc_kernel(const float* __restrict__ W) {
    __shared__ float s[32][33];
    const int n0 = blockIdx.x * 32, k0 = blockIdx.y * 32;
    const int tx = threadIdx.x, ty0 = threadIdx.y;     // block 32x8
#pragma unroll
    for (int dy = 0; dy < 32; dy += 8)
        s[ty0 + dy][tx] = W[(size_t)(k0 + ty0 + dy) * DLAT + n0 + tx];
    __syncthreads();
#pragma unroll
    for (int dy = 0; dy < 32; dy += 8) {
        int ty = ty0 + dy;
        float v = s[tx][ty];
        size_t o = (size_t)(n0 + ty) * DIN + k0 + tx;
        g_WT[o]  = v;
        g_Bth[o] = __float2half_rn(v);
    }
}

// ---------------------------------------------------------------------------
// fp16 tensor-core GEMM (mma.sync): H = Ah @ Bth^T (+bias), fp16 out
// BM=128, BN=128, BK=32 halfs, 4-stage cp.async pipeline, 256 threads.
// ---------------------------------------------------------------------------
#define GNIT (DIN / 32)     // 24

__global__ __launch_bounds__(256, 2)
void gemm_fp16_kernel(const float* __restrict__ bias) {
    extern __shared__ char sm[];
    const uint32_t sbase = smem_u32(sm);
    const int tid  = threadIdx.x;
    const int lane = tid & 31;
    const int wid  = tid >> 5;
    const int wm   = wid & 1;
    const int wn   = wid >> 1;
    const int bn   = blockIdx.x * 128;
    const int bm   = blockIdx.y * 128;

    float acc[4][4][4];
#pragma unroll
    for (int f = 0; f < 4; f++)
#pragma unroll
        for (int g = 0; g < 4; g++)
#pragma unroll
            for (int q = 0; q < 4; q++) acc[f][g][q] = 0.0f;

    auto load_stage = [&](int it) {
        const int s = it & 3;
        const int koff = it * 32;
        const uint32_t base = sbase + s * 16384;
#pragma unroll
        for (int q = 0; q < 4; q++) {
            int idx = tid + q * 256;
            int isB = idx >= 512;
            int id2 = idx - (isB ? 512 : 0);
            int r  = id2 >> 2;
            int ch = id2 & 3;
            const __half* src = isB
                ? (g_Bth + (size_t)(bn + r) * DIN + koff + ch * 8)
                : (g_Ah  + (size_t)(bm + r) * DIN + koff + ch * 8);
            uint32_t dst = base + (isB ? 8192 : 0) + r * 64 +
                           ((ch ^ ((r >> 1) & 3)) << 4);
            CP_ASYNC16(dst, src);
        }
        CP_COMMIT();
    };

    load_stage(0);
    load_stage(1);
    load_stage(2);

    for (int it = 0; it < GNIT; it++) {
        if (it + 3 < GNIT) CP_WAIT(2); else CP_WAIT(0);
        __syncthreads();
        if (it + 3 < GNIT) load_stage(it + 3);

        const uint32_t sA = sbase + (it & 3) * 16384;
        const uint32_t sB = sA + 8192;
#pragma unroll
        for (int ks = 0; ks < 2; ks++) {
            uint32_t a[4][4], b[4][2];
#pragma unroll
            for (int f = 0; f < 4; f++) {
                int q  = lane >> 3;
                int r  = wm * 64 + f * 16 + (lane & 7) + ((q & 1) << 3);
                int ch = ks * 2 + (q >> 1);
                uint32_t addr = sA + r * 64 + ((ch ^ ((r >> 1) & 3)) << 4);
                LDMATRIX_X4(a[f][0], a[f][1], a[f][2], a[f][3], addr);
            }
#pragma unroll
            for (int p = 0; p < 2; p++) {
                int q  = lane >> 3;
                int n  = wn * 32 + p * 16 + ((q >> 1) << 3) + (lane & 7);
                int ch = ks * 2 + (q & 1);
                uint32_t addr = sB + n * 64 + ((ch ^ ((n >> 1) & 3)) << 4);
                LDMATRIX_X4(b[2 * p][0], b[2 * p][1], b[2 * p + 1][0], b[2 * p + 1][1], addr);
            }
#pragma unroll
            for (int f = 0; f < 4; f++)
#pragma unroll
                for (int g = 0; g < 4; g++)
                    MMA16816(acc[f][g][0], acc[f][g][1], acc[f][g][2], acc[f][g][3],
                             a[f][0], a[f][1], a[f][2], a[f][3],
                             b[g][0], b[g][1]);
        }
        __syncthreads();
    }

#pragma unroll
    for (int f = 0; f < 4; f++) {
#pragma unroll
        for (int g = 0; g < 4; g++) {
            int r0 = bm + wm * 64 + f * 16 + (lane >> 2);
            int c0 = bn + wn * 32 + g * 8 + (lane & 3) * 2;
            float b0 = bias[c0], b1 = bias[c0 + 1];
            __half2 h0 = __floats2half2_rn(acc[f][g][0] + b0, acc[f][g][1] + b1);
            __half2 h1 = __floats2half2_rn(acc[f][g][2] + b0, acc[f][g][3] + b1);
            *(__half2*)(g_H + (size_t)r0 * DLAT + c0)       = h0;
            *(__half2*)(g_H + (size_t)(r0 + 8) * DLAT + c0) = h1;
        }
    }
}

// ---------------------------------------------------------------------------
// Top-96 candidate selection per row -- register-resident keys.
// ---------------------------------------------------------------------------
__device__ __forceinline__ unsigned f2key16(unsigned u) {
    return (u & 0x8000u) ? ((~u) & 0xFFFFu) : (u | 0x8000u);
}

// Warp-0 collective: pick highest bucket b with suffix-count >= target.
// Writes {bucket, remainder} to out[0], out[1].
__device__ __forceinline__ void select_bucket_warp0(const int* hist, int target, int* out) {
    const int lane = threadIdx.x;   // caller guarantees tid < 32
    int h[8];
    int t = 0;
    const int base = 255 - lane * 8;            // lane 0 owns bins 255..248
#pragma unroll
    for (int j = 0; j < 8; j++) { h[j] = hist[base - j]; t += h[j]; }
    int inc = t;
#pragma unroll
    for (int o = 1; o < 32; o <<= 1) {
        int v = __shfl_up_sync(0xFFFFFFFFu, inc, o);
        if (lane >= o) inc += v;
    }
    const int ex = inc - t;                     // suffix count of higher lanes' bins
    int fb = -1, fr = 0, cum = ex;
#pragma unroll
    for (int j = 0; j < 8; j++) {
        cum += h[j];
        if (fb < 0 && cum >= target) { fb = base - j; fr = target - (cum - h[j]); }
    }
    unsigned m = __ballot_sync(0xFFFFFFFFu, fb >= 0);
    int src = __ffs(m) - 1;
    int b   = __shfl_sync(0xFFFFFFFFu, fb, src);
    int r   = __shfl_sync(0xFFFFFFFFu, fr, src);
    if (lane == 0) { out[0] = b; out[1] = r; }
}

__global__ __launch_bounds__(256)
void topk16_kernel() {
    __shared__ int hist[256];
    __shared__ int sel_s[2];
    __shared__ int wsum[8];
    __shared__ int wbase[9];

    const int tid  = threadIdx.x;
    const int lane = tid & 31;
    const int wrp  = tid >> 5;
    const int row  = blockIdx.x;
    const uint4* hrow = (const uint4*)(g_H + (size_t)row * DLAT);

    // load 48 halfs -> 24 packed keys (registers)
    uint32_t kp[24];
#pragma unroll
    for (int q = 0; q < 6; q++) {
        uint4 v = hrow[tid + q * 256];
        uint32_t w[4] = {v.x, v.y, v.z, v.w};
#pragma unroll
        for (int p = 0; p < 4; p++) {
            uint32_t lo = f2key16(w[p] & 0xFFFFu);
            uint32_t hi = f2key16(w[p] >> 16);
            kp[q * 4 + p] = lo | (hi << 16);
        }
    }
    hist[tid] = 0;
    __syncthreads();

    // pass 1: high-byte histogram
#pragma unroll
    for (int j = 0; j < 24; j++) {
        atomicAdd(&hist[(kp[j] >> 8) & 0xFFu], 1);
        atomicAdd(&hist[kp[j] >> 24], 1);
    }
    __syncthreads();
    if (tid < 32) select_bucket_warp0(hist, CAND_TARGET, sel_s);
    __syncthreads();
    const int b1   = sel_s[0];
    const int kRem = sel_s[1];
    __syncthreads();

    // pass 2: low byte within bucket b1 (rare hits)
    hist[tid] = 0;
    __syncthreads();
#pragma unroll
    for (int j = 0; j < 24; j++) {
        uint32_t k0 = kp[j] & 0xFFFFu, k1 = kp[j] >> 16;
        if ((int)(k0 >> 8) == b1) atomicAdd(&hist[k0 & 255], 1);
        if ((int)(k1 >> 8) == b1) atomicAdd(&hist[k1 & 255], 1);
    }
    __syncthreads();
    if (tid < 32) select_bucket_warp0(hist, kRem, sel_s);
    __syncthreads();
    const unsigned thr = ((unsigned)b1 << 8) | (unsigned)sel_s[0];

    // count per thread (registers only)
    int c = 0;
#pragma unroll
    for (int j = 0; j < 24; j++) {
        c += ((kp[j] & 0xFFFFu) >= thr);
        c += ((kp[j] >> 16) >= thr);
    }
    // two-level exclusive scan over 256 threads
    int inc = c;
#pragma unroll
    for (int o = 1; o < 32; o <<= 1) {
        int v = __shfl_up_sync(0xFFFFFFFFu, inc, o);
        if (lane >= o) inc += v;
    }
    if (lane == 31) wsum[wrp] = inc;
    __syncthreads();
    if (tid == 0) {
        int s = 0;
        for (int w = 0; w < 8; w++) { wbase[w] = s; s += wsum[w]; }
        wbase[8] = s;
        g_ncand[row] = (s < CAND_CAP) ? s : CAND_CAP;
    }
    __syncthreads();
    int base = wbase[wrp] + inc - c;

    // deterministic emit (canonical per-thread order)
    int l = 0;
#pragma unroll
    for (int j = 0; j < 24; j++) {
        const int idx0 = (tid + (j >> 2) * 256) * 8 + (j & 3) * 2;
        uint32_t k0 = kp[j] & 0xFFFFu, k1 = kp[j] >> 16;
        if (k0 >= thr) {
            int s = base + l; l++;
            if (s < CAND_CAP) g_cand[(size_t)row * CAND_CAP + s] = idx0;
        }
        if (k1 >= thr) {
            int s = base + l; l++;
            if (s < CAND_CAP) g_cand[(size_t)row * CAND_CAP + s] = idx0 + 1;
        }
    }
}

// ---------------------------------------------------------------------------
// Exact fp32 rescore: one warp per candidate + exact top-64 + z write
// ---------------------------------------------------------------------------
__global__ __launch_bounds__(128)
void rescore_kernel(const float* __restrict__ x,
                    const float* __restrict__ b_enc,
                    float* __restrict__ z) {
    __shared__ float xs[DIN];
    __shared__ int   cidx[CAND_CAP];
    __shared__ float cval[CAND_CAP];
    __shared__ int   slotArr[CAND_CAP];
    __shared__ unsigned char sel[CAND_CAP];

    const int tid  = threadIdx.x;
    const int lane = tid & 31;
    const int wid  = tid >> 5;
    const int row  = blockIdx.x;
    const int nc   = g_ncand[row];

    for (int i = tid; i < DIN / 4; i += 128)
        *(float4*)&xs[i * 4] = *(const float4*)&x[(size_t)row * DIN + i * 4];
    for (int i = tid; i < nc; i += 128)
        cidx[i] = g_cand[(size_t)row * CAND_CAP + i];
    __syncthreads();

    const float4* x4 = (const float4*)xs;
    for (int t = wid; t < nc; t += 4) {
        const int j = cidx[t];
        const float4* w4 = (const float4*)(g_WT + (size_t)j * DIN);
        float acc = 0.0f;
#pragma unroll
        for (int q = 0; q < 6; q++) {
            const int p = lane + q * 32;
            float4 wv = w4[p];
            float4 xv = x4[p];
            acc = fmaf(wv.x, xv.x, acc);
            acc = fmaf(wv.y, xv.y, acc);
            acc = fmaf(wv.z, xv.z, acc);
            acc = fmaf(wv.w, xv.w, acc);
        }
#pragma unroll
        for (int o = 16; o; o >>= 1)
            acc += __shfl_xor_sync(0xFFFFFFFFu, acc, o);
        if (lane == 0) cval[t] = acc + b_enc[j];
    }
    __syncthreads();

    for (int t = tid; t < nc; t += 128) {
        const float v = cval[t];
        const int   j = cidx[t];
        int r = 0;
        for (int q = 0; q < nc; q++) {
            float vq = cval[q];
            r += (vq > v) || (vq == v && cidx[q] < j);
        }
        sel[t] = (r < KTOP) ? 1 : 0;
    }
    __syncthreads();
    if (tid == 0) {
        int s = 0;
        for (int q = 0; q < nc; q++) { slotArr[q] = s; s += sel[q]; }
    }
    __syncthreads();

    float4* zr4 = (float4*)(z + (size_t)row * DLAT);
    const float4 zf = {0.f, 0.f, 0.f, 0.f};
    for (int i = tid; i < DLAT / 4; i += 128) zr4[i] = zf;
    __syncthreads();
    for (int t = tid; t < nc; t += 128) {
        if (sel[t]) {
            int s = slotArr[t];
            g_topk_idx[row * KTOP + s] = cidx[t];
            g_topk_val[row * KTOP + s] = cval[t];
            z[(size_t)row * DLAT + cidx[t]] = cval[t];
        }
    }
}

// ---------------------------------------------------------------------------
// Sparse decoder, fp32 W_dec
// ---------------------------------------------------------------------------
__global__ __launch_bounds__(256)
void decoder_kernel(const float* __restrict__ Wd,
                    const float* __restrict__ bd,
                    float* __restrict__ recon) {
    __shared__ int   sidx[KTOP];
    __shared__ float sval[KTOP];
    const int tid = threadIdx.x;
    const int row = blockIdx.x;
    if (tid < KTOP) {
        sidx[tid] = g_topk_idx[row * KTOP + tid];
        sval[tid] = g_topk_val[row * KTOP + tid];
    }
    __syncthreads();

    float a0 = 0.0f, a1 = 0.0f, a2 = 0.0f;
#pragma unroll 4
    for (int i = 0; i < KTOP; i++) {
        const float* wr = Wd + (size_t)sidx[i] * DIN;
        const float  v  = sval[i];
        a0 = fmaf(v, wr[tid],       a0);
        a1 = fmaf(v, wr[tid + 256], a1);
        a2 = fmaf(v, wr[tid + 512], a2);
    }
    const size_t ro = (size_t)row * DIN;
    recon[ro + tid]       = a0 + bd[tid];
    recon[ro + tid + 256] = a1 + bd[tid + 256];
    recon[ro + tid + 512] = a2 + bd[tid + 512];
}

// ---------------------------------------------------------------------------
extern "C" void kernel_launch(void* const* d_in, const int* in_sizes, int n_in,
                              void* d_out, int out_size) {
    const float* x     = (const float*)d_in[0];
    const float* W_enc = (const float*)d_in[1];
    const float* b_enc = (const float*)d_in[2];
    const float* W_dec = (const float*)d_in[3];
    const float* b_dec = (const float*)d_in[4];

    float* recon = (float*)d_out;
    float* z     = (float*)d_out + (size_t)NB * DIN;

    conv_x_kernel<<<(NB * DIN + 255) / 256, 256>>>(x);
    conv_wenc_kernel<<<dim3(DLAT / 32, DIN / 32), dim3(32, 8)>>>(W_enc);

    const int gemm_smem = 4 * 16384;
    cudaFuncSetAttribute(gemm_fp16_kernel,
                         cudaFuncAttributeMaxDynamicSharedMemorySize, gemm_smem);
    gemm_fp16_kernel<<<dim3(DLAT / 128, NB / 128), 256, gemm_smem>>>(b_enc);

    topk16_kernel<<<NB, 256>>>();

    rescore_kernel<<<NB, 128>>>(x, b_enc, z);

    decoder_kernel<<<NB, 256>>>(W_dec, b_dec, recon);
}